// round 3
// baseline (speedup 1.0000x reference)
#include <cuda_runtime.h>

#define BB 32
#define NN 300
#define HH 1024
#define WW 1024
#define HWP (HH * WW)
#define NB (BB * NN)          // 9600 boxes total
#define ROWS_PER_BLK 8
#define PAIRS (ROWS_PER_BLK / 2)
#define THREADS 256
#define NWARPS (THREADS / 32)

// Scratch: per-box accumulators. Zero-initialized at module load; the reduce
// kernel re-zeroes it after consuming, so every graph replay starts clean.
__device__ float g_boxsum[NB];

__device__ __forceinline__ int4 box_coords(const float4 bx) {
    // cxcywh -> xyxy pixel indices, trunc toward zero (C cast == jnp.trunc
    // for this range), clamp to [0, dim-1]. Validity handled in reduce.
    int x1 = min(max((int)((bx.x - 0.5f * bx.z) * (float)WW), 0), WW - 1);
    int x2 = min(max((int)((bx.x + 0.5f * bx.z) * (float)WW), 0), WW - 1);
    int y1 = min(max((int)((bx.y - 0.5f * bx.w) * (float)HH), 0), HH - 1);
    int y2 = min(max((int)((bx.y + 0.5f * bx.w) * (float)HH), 0), HH - 1);
    return make_int4(x1, x2, y1, y2);   // (x1, x2, y1, y2)
}

// ---------------------------------------------------------------------------
// Strip kernel: one CTA per (batch, 8-row strip). Per row-PAIR: build two
// exclusive row prefixes of (footpath - driveway) in SMEM via interleaved
// warp scans (shared barriers), then each thread folds S[x2]-S[x1] for its
// <=2 owned boxes into registers. One atomicAdd per (box, strip) at the end.
// ---------------------------------------------------------------------------
__global__ __launch_bounds__(THREADS)
void strip_kernel(const float* __restrict__ seg,
                  const float* __restrict__ boxes) {
    __shared__ float S0[WW + 1];
    __shared__ float S1[WW + 1];
    __shared__ float ws0[NWARPS];
    __shared__ float ws1[NWARPS];

    const int b    = blockIdx.x / (HH / ROWS_PER_BLK);
    const int rb   = blockIdx.x % (HH / ROWS_PER_BLK);
    const int row0 = rb * ROWS_PER_BLK;
    const int tid  = threadIdx.x;
    const int lane = tid & 31;
    const int wid  = tid >> 5;

    // Owned boxes (<=2 per thread): compute coords locally, no prep pass.
    const int n0 = tid;
    const int n1 = tid + THREADS;
    int4 c0 = box_coords(((const float4*)boxes)[b * NN + n0]);
    int4 c1 = (n1 < NN) ? box_coords(((const float4*)boxes)[b * NN + n1])
                        : make_int4(0, 0, 0, 0);   // y1=y2=0 -> never matches
    float acc0 = 0.0f, acc1 = 0.0f;

    const float4* dptr = (const float4*)(seg + (size_t)b * 3 * HWP + 1 * HWP);
    const float4* fptr = (const float4*)(seg + (size_t)b * 3 * HWP + 2 * HWP);

    // Prefetch first pair of rows (4 LDG.128 in flight per thread).
    float4 dA, fA, dB, fB;
    {
        int ia = row0 * (WW / 4) + tid;
        int ib = ia + (WW / 4);
        dA = dptr[ia]; fA = fptr[ia];
        dB = dptr[ib]; fB = fptr[ib];
    }

    #pragma unroll
    for (int p = 0; p < PAIRS; ++p) {
        const int row = row0 + 2 * p;

        float a0 = fA.x - dA.x;
        float a1 = a0 + (fA.y - dA.y);
        float a2 = a1 + (fA.z - dA.z);
        float a3 = a2 + (fA.w - dA.w);
        float b0 = fB.x - dB.x;
        float b1 = b0 + (fB.y - dB.y);
        float b2 = b1 + (fB.z - dB.z);
        float b3 = b2 + (fB.w - dB.w);

        // Prefetch next pair while scanning this one.
        float4 dA2, fA2, dB2, fB2;
        if (p + 1 < PAIRS) {
            int ia = (row + 2) * (WW / 4) + tid;
            int ib = ia + (WW / 4);
            dA2 = dptr[ia]; fA2 = fptr[ia];
            dB2 = dptr[ib]; fB2 = fptr[ib];
        }

        // Two interleaved warp-inclusive scans (shared shfl latency).
        float tA = a3, tB = b3;
        #pragma unroll
        for (int o = 1; o < 32; o <<= 1) {
            float vA = __shfl_up_sync(0xffffffffu, tA, o);
            float vB = __shfl_up_sync(0xffffffffu, tB, o);
            if (lane >= o) { tA += vA; tB += vB; }
        }
        if (lane == 31) { ws0[wid] = tA; ws1[wid] = tB; }
        __syncthreads();

        float wb0 = 0.0f, wb1 = 0.0f;
        #pragma unroll
        for (int wv = 0; wv < NWARPS; ++wv)
            if (wv < wid) { wb0 += ws0[wv]; wb1 += ws1[wv]; }

        float base0 = wb0 + (tA - a3);
        float base1 = wb1 + (tB - b3);
        int xi = tid << 2;
        S0[xi + 1] = base0 + a0;
        S0[xi + 2] = base0 + a1;
        S0[xi + 3] = base0 + a2;
        S0[xi + 4] = base0 + a3;
        S1[xi + 1] = base1 + b0;
        S1[xi + 2] = base1 + b1;
        S1[xi + 3] = base1 + b2;
        S1[xi + 4] = base1 + b3;
        if (tid == 0) { S0[0] = 0.0f; S1[0] = 0.0f; }
        __syncthreads();

        // Box accumulation for both rows (register-resident).
        if (row     >= c0.z && row     < c0.w) acc0 += S0[c0.y] - S0[c0.x];
        if (row + 1 >= c0.z && row + 1 < c0.w) acc0 += S1[c0.y] - S1[c0.x];
        if (row     >= c1.z && row     < c1.w) acc1 += S0[c1.y] - S0[c1.x];
        if (row + 1 >= c1.z && row + 1 < c1.w) acc1 += S1[c1.y] - S1[c1.x];
        __syncthreads();   // protect S / ws before next pair overwrites

        dA = dA2; fA = fA2; dB = dB2; fB = fB2;
    }

    if (acc0 != 0.0f)            atomicAdd(&g_boxsum[b * NN + n0], acc0);
    if (n1 < NN && acc1 != 0.0f) atomicAdd(&g_boxsum[b * NN + n1], acc1);
}

// ---------------------------------------------------------------------------
// Reduce: recompute validity/weight per box, fold in box sums, write scalar,
// and re-zero g_boxsum for the next graph replay.
// ---------------------------------------------------------------------------
__global__ void reduce_kernel(const float* __restrict__ boxes,
                              const float* __restrict__ conf,
                              float* __restrict__ out) {
    const int tid = threadIdx.x;
    float s = 0.0f;
    for (int i = tid; i < NB; i += THREADS) {
        int4 c  = box_coords(((const float4*)boxes)[i]);
        float cf = conf[i];
        bool valid = (cf >= 0.3f) && (c.y > c.x) && (c.w > c.z);
        float v = g_boxsum[i];
        g_boxsum[i] = 0.0f;                       // reset for next replay
        if (valid) {
            float area = (float)((c.w - c.z) * (c.y - c.x));
            s += fmaxf(v, 0.0f) * cf / area;      // relu((f-d)/area)*conf
        }
    }
    __shared__ float sm[NWARPS];
    #pragma unroll
    for (int o = 16; o > 0; o >>= 1) s += __shfl_down_sync(0xffffffffu, s, o);
    if ((tid & 31) == 0) sm[tid >> 5] = s;
    __syncthreads();
    if (tid < NWARPS) {
        s = sm[tid];
        #pragma unroll
        for (int o = NWARPS / 2; o > 0; o >>= 1)
            s += __shfl_down_sync(0xffu, s, o);
        if (tid == 0) out[0] = s / (float)NB;
    }
}

// ---------------------------------------------------------------------------
extern "C" void kernel_launch(void* const* d_in, const int* in_sizes, int n_in,
                              void* d_out, int out_size) {
    const float* boxes = (const float*)d_in[0];   // (32,300,4)
    const float* conf  = (const float*)d_in[1];   // (32,300)
    const float* seg   = (const float*)d_in[2];   // (32,3,1024,1024)
    float* out = (float*)d_out;

    strip_kernel<<<BB * (HH / ROWS_PER_BLK), THREADS>>>(seg, boxes);
    reduce_kernel<<<1, THREADS>>>(boxes, conf, out);
}

// round 4
// speedup vs baseline: 1.4004x; 1.4004x over previous
#include <cuda_runtime.h>

#define BB 32
#define NN 300
#define HH 1024
#define WW 1024
#define HWP (HH * WW)
#define NB (BB * NN)          // 9600 boxes total
#define ROWS_PER_BLK 8
#define PAIRS (ROWS_PER_BLK / 2)
#define THREADS 256
#define NWARPS (THREADS / 32)

// Scratch: per-box accumulators + scalar total. Zero-initialized at module
// load; reduce/finalize re-zero them, so every graph replay starts clean.
__device__ float g_boxsum[NB];
__device__ float g_total;

__device__ __forceinline__ int4 box_coords(const float4 bx) {
    // cxcywh -> xyxy pixel indices, trunc toward zero (C cast == jnp.trunc
    // for this range), clamp to [0, dim-1]. Validity handled in reduce.
    int x1 = min(max((int)((bx.x - 0.5f * bx.z) * (float)WW), 0), WW - 1);
    int x2 = min(max((int)((bx.x + 0.5f * bx.z) * (float)WW), 0), WW - 1);
    int y1 = min(max((int)((bx.y - 0.5f * bx.w) * (float)HH), 0), HH - 1);
    int y2 = min(max((int)((bx.y + 0.5f * bx.w) * (float)HH), 0), HH - 1);
    return make_int4(x1, x2, y1, y2);   // (x1, x2, y1, y2)
}

// ---------------------------------------------------------------------------
// Strip kernel: one CTA per (batch, 8-row strip). Per row-PAIR: build two
// exclusive row prefixes of (footpath - driveway) in SMEM via interleaved
// warp scans (shared barriers), then each thread folds S[x2]-S[x1] for its
// <=2 owned boxes into registers. One atomicAdd per (box, strip) at the end.
// ---------------------------------------------------------------------------
__global__ __launch_bounds__(THREADS)
void strip_kernel(const float* __restrict__ seg,
                  const float* __restrict__ boxes) {
    __shared__ float S0[WW + 1];
    __shared__ float S1[WW + 1];
    __shared__ float ws0[NWARPS];
    __shared__ float ws1[NWARPS];

    const int b    = blockIdx.x / (HH / ROWS_PER_BLK);
    const int rb   = blockIdx.x % (HH / ROWS_PER_BLK);
    const int row0 = rb * ROWS_PER_BLK;
    const int tid  = threadIdx.x;
    const int lane = tid & 31;
    const int wid  = tid >> 5;

    // Owned boxes (<=2 per thread): compute coords locally, no prep pass.
    const int n0 = tid;
    const int n1 = tid + THREADS;
    int4 c0 = box_coords(((const float4*)boxes)[b * NN + n0]);
    int4 c1 = (n1 < NN) ? box_coords(((const float4*)boxes)[b * NN + n1])
                        : make_int4(0, 0, 0, 0);   // y1=y2=0 -> never matches
    float acc0 = 0.0f, acc1 = 0.0f;

    const float4* dptr = (const float4*)(seg + (size_t)b * 3 * HWP + 1 * HWP);
    const float4* fptr = (const float4*)(seg + (size_t)b * 3 * HWP + 2 * HWP);

    // Prefetch first pair of rows (4 LDG.128 in flight per thread).
    float4 dA, fA, dB, fB;
    {
        int ia = row0 * (WW / 4) + tid;
        int ib = ia + (WW / 4);
        dA = dptr[ia]; fA = fptr[ia];
        dB = dptr[ib]; fB = fptr[ib];
    }

    #pragma unroll
    for (int p = 0; p < PAIRS; ++p) {
        const int row = row0 + 2 * p;

        float a0 = fA.x - dA.x;
        float a1 = a0 + (fA.y - dA.y);
        float a2 = a1 + (fA.z - dA.z);
        float a3 = a2 + (fA.w - dA.w);
        float b0 = fB.x - dB.x;
        float b1 = b0 + (fB.y - dB.y);
        float b2 = b1 + (fB.z - dB.z);
        float b3 = b2 + (fB.w - dB.w);

        // Prefetch next pair while scanning this one.
        float4 dA2, fA2, dB2, fB2;
        if (p + 1 < PAIRS) {
            int ia = (row + 2) * (WW / 4) + tid;
            int ib = ia + (WW / 4);
            dA2 = dptr[ia]; fA2 = fptr[ia];
            dB2 = dptr[ib]; fB2 = fptr[ib];
        }

        // Two interleaved warp-inclusive scans (shared shfl latency).
        float tA = a3, tB = b3;
        #pragma unroll
        for (int o = 1; o < 32; o <<= 1) {
            float vA = __shfl_up_sync(0xffffffffu, tA, o);
            float vB = __shfl_up_sync(0xffffffffu, tB, o);
            if (lane >= o) { tA += vA; tB += vB; }
        }
        if (lane == 31) { ws0[wid] = tA; ws1[wid] = tB; }
        __syncthreads();

        float wb0 = 0.0f, wb1 = 0.0f;
        #pragma unroll
        for (int wv = 0; wv < NWARPS; ++wv)
            if (wv < wid) { wb0 += ws0[wv]; wb1 += ws1[wv]; }

        float base0 = wb0 + (tA - a3);
        float base1 = wb1 + (tB - b3);
        int xi = tid << 2;
        S0[xi + 1] = base0 + a0;
        S0[xi + 2] = base0 + a1;
        S0[xi + 3] = base0 + a2;
        S0[xi + 4] = base0 + a3;
        S1[xi + 1] = base1 + b0;
        S1[xi + 2] = base1 + b1;
        S1[xi + 3] = base1 + b2;
        S1[xi + 4] = base1 + b3;
        if (tid == 0) { S0[0] = 0.0f; S1[0] = 0.0f; }
        __syncthreads();

        // Box accumulation for both rows (register-resident).
        if (row     >= c0.z && row     < c0.w) acc0 += S0[c0.y] - S0[c0.x];
        if (row + 1 >= c0.z && row + 1 < c0.w) acc0 += S1[c0.y] - S1[c0.x];
        if (row     >= c1.z && row     < c1.w) acc1 += S0[c1.y] - S0[c1.x];
        if (row + 1 >= c1.z && row + 1 < c1.w) acc1 += S1[c1.y] - S1[c1.x];
        __syncthreads();   // protect S / ws before next pair overwrites

        dA = dA2; fA = fA2; dB = dB2; fB = fB2;
    }

    if (acc0 != 0.0f)            atomicAdd(&g_boxsum[b * NN + n0], acc0);
    if (n1 < NN && acc1 != 0.0f) atomicAdd(&g_boxsum[b * NN + n1], acc1);
}

// ---------------------------------------------------------------------------
// Reduce: 38 CTAs, ONE box per thread (full wave, no serial loop). Each
// thread recomputes validity/weight, folds in its box sum, resets g_boxsum.
// One atomicAdd per CTA into g_total.
// ---------------------------------------------------------------------------
__global__ __launch_bounds__(THREADS)
void reduce_kernel(const float* __restrict__ boxes,
                   const float* __restrict__ conf) {
    const int i = blockIdx.x * THREADS + threadIdx.x;
    float s = 0.0f;
    if (i < NB) {
        float v = g_boxsum[i];
        g_boxsum[i] = 0.0f;                       // reset for next replay
        int4 c   = box_coords(((const float4*)boxes)[i]);
        float cf = conf[i];
        if ((cf >= 0.3f) && (c.y > c.x) && (c.w > c.z)) {
            float area = (float)((c.w - c.z) * (c.y - c.x));
            s = fmaxf(v, 0.0f) * cf / area;       // relu((f-d)/area)*conf
        }
    }
    __shared__ float sm[NWARPS];
    #pragma unroll
    for (int o = 16; o > 0; o >>= 1) s += __shfl_down_sync(0xffffffffu, s, o);
    if ((threadIdx.x & 31) == 0) sm[threadIdx.x >> 5] = s;
    __syncthreads();
    if (threadIdx.x < 32) {
        s = (threadIdx.x < NWARPS) ? sm[threadIdx.x] : 0.0f;
        #pragma unroll
        for (int o = NWARPS / 2; o > 0; o >>= 1)
            s += __shfl_down_sync(0xffffffffu, s, o);
        if (threadIdx.x == 0 && s != 0.0f) atomicAdd(&g_total, s);
    }
}

// ---------------------------------------------------------------------------
// Finalize: write scalar output, re-zero g_total for the next graph replay.
// ---------------------------------------------------------------------------
__global__ void finalize_kernel(float* __restrict__ out) {
    out[0] = g_total / (float)NB;
    g_total = 0.0f;
}

// ---------------------------------------------------------------------------
extern "C" void kernel_launch(void* const* d_in, const int* in_sizes, int n_in,
                              void* d_out, int out_size) {
    const float* boxes = (const float*)d_in[0];   // (32,300,4)
    const float* conf  = (const float*)d_in[1];   // (32,300)
    const float* seg   = (const float*)d_in[2];   // (32,3,1024,1024)
    float* out = (float*)d_out;

    strip_kernel<<<BB * (HH / ROWS_PER_BLK), THREADS>>>(seg, boxes);
    reduce_kernel<<<(NB + THREADS - 1) / THREADS, THREADS>>>(boxes, conf);
    finalize_kernel<<<1, 1>>>(out);
}

// round 6
// speedup vs baseline: 1.5032x; 1.0734x over previous
#include <cuda_runtime.h>

#define BB 32
#define NN 300
#define HH 1024
#define WW 1024
#define HWP (HH * WW)
#define NB (BB * NN)          // 9600 boxes total
#define ROWS_PER_BLK 8
#define PAIRS (ROWS_PER_BLK / 2)
#define THREADS 256
#define NWARPS (THREADS / 32)
#define STAGES 2

// Scratch: per-box accumulators + scalar total. Zero-initialized at module
// load; reduce/finalize re-zero them, so every graph replay starts clean.
__device__ float g_boxsum[NB];
__device__ float g_total;

__device__ __forceinline__ void cp16(void* dst_smem, const void* src) {
    unsigned d = (unsigned)__cvta_generic_to_shared(dst_smem);
    asm volatile("cp.async.cg.shared.global [%0], [%1], 16;" :: "r"(d), "l"(src));
}
__device__ __forceinline__ void cp_commit() {
    asm volatile("cp.async.commit_group;" ::: "memory");
}
template <int N>
__device__ __forceinline__ void cp_wait() {
    asm volatile("cp.async.wait_group %0;" :: "n"(N) : "memory");
}

__device__ __forceinline__ int4 box_coords(const float4 bx) {
    // cxcywh -> xyxy pixel indices, trunc toward zero (C cast == jnp.trunc
    // for this range), clamp to [0, dim-1]. Validity handled in reduce.
    int x1 = min(max((int)((bx.x - 0.5f * bx.z) * (float)WW), 0), WW - 1);
    int x2 = min(max((int)((bx.x + 0.5f * bx.z) * (float)WW), 0), WW - 1);
    int y1 = min(max((int)((bx.y - 0.5f * bx.w) * (float)HH), 0), HH - 1);
    int y2 = min(max((int)((bx.y + 0.5f * bx.w) * (float)HH), 0), HH - 1);
    return make_int4(x1, x2, y1, y2);   // (x1, x2, y1, y2)
}

// ---------------------------------------------------------------------------
// Strip kernel: one CTA per (batch, 8-row strip). Tiles stage through SMEM
// via cp.async double-buffer (registers never hold in-flight loads). Per
// row-PAIR: two interleaved warp scans build exclusive prefixes S0/S1; each
// thread folds S[x2]-S[x1] for its <=2 owned boxes into registers. Two
// barriers per pair. One atomicAdd per (box, strip) at the end.
// ---------------------------------------------------------------------------
__global__ __launch_bounds__(THREADS, 5)
void strip_kernel(const float* __restrict__ seg,
                  const float* __restrict__ boxes) {
    __shared__ float4 tile[STAGES][4][THREADS];  // [stage][dA,fA,dB,fB][tid]
    __shared__ float S0[WW + 1];
    __shared__ float S1[WW + 1];
    __shared__ float ws0[NWARPS];
    __shared__ float ws1[NWARPS];

    const int b    = blockIdx.x / (HH / ROWS_PER_BLK);
    const int rb   = blockIdx.x % (HH / ROWS_PER_BLK);
    const int row0 = rb * ROWS_PER_BLK;
    const int tid  = threadIdx.x;
    const int lane = tid & 31;
    const int wid  = tid >> 5;

    const float* dbase = seg + (size_t)b * 3 * HWP + 1 * HWP;
    const float* fbase = seg + (size_t)b * 3 * HWP + 2 * HWP;

    // Prologue: issue stages 0 and 1 (one commit group per stage).
    {
        int ia = row0 * WW + tid * 4;
        cp16(&tile[0][0][tid], dbase + ia);
        cp16(&tile[0][1][tid], fbase + ia);
        cp16(&tile[0][2][tid], dbase + ia + WW);
        cp16(&tile[0][3][tid], fbase + ia + WW);
        cp_commit();
        ia += 2 * WW;
        cp16(&tile[1][0][tid], dbase + ia);
        cp16(&tile[1][1][tid], fbase + ia);
        cp16(&tile[1][2][tid], dbase + ia + WW);
        cp16(&tile[1][3][tid], fbase + ia + WW);
        cp_commit();
    }

    // Owned boxes (<=2 per thread): compute coords locally (overlaps with
    // the in-flight cp.async stages).
    const int n0 = tid;
    const int n1 = tid + THREADS;
    int4 c0 = box_coords(((const float4*)boxes)[b * NN + n0]);
    int4 c1 = (n1 < NN) ? box_coords(((const float4*)boxes)[b * NN + n1])
                        : make_int4(0, 0, 0, 0);   // y1=y2=0 -> never matches
    float acc0 = 0.0f, acc1 = 0.0f;

    #pragma unroll
    for (int p = 0; p < PAIRS; ++p) {
        const int row = row0 + 2 * p;
        const int s   = p & 1;

        // Stage p complete (each thread reads only bytes its own cp.async
        // wrote, so wait_group suffices -- no barrier).
        cp_wait<1>();
        float4 dA = tile[s][0][tid];
        float4 fA = tile[s][1][tid];
        float4 dB = tile[s][2][tid];
        float4 fB = tile[s][3][tid];

        float a0 = fA.x - dA.x;
        float a1 = a0 + (fA.y - dA.y);
        float a2 = a1 + (fA.z - dA.z);
        float a3 = a2 + (fA.w - dA.w);
        float b0 = fB.x - dB.x;
        float b1 = b0 + (fB.y - dB.y);
        float b2 = b1 + (fB.z - dB.z);
        float b3 = b2 + (fB.w - dB.w);

        // Two interleaved warp-inclusive scans (shared shfl latency).
        float tA = a3, tB = b3;
        #pragma unroll
        for (int o = 1; o < 32; o <<= 1) {
            float vA = __shfl_up_sync(0xffffffffu, tA, o);
            float vB = __shfl_up_sync(0xffffffffu, tB, o);
            if (lane >= o) { tA += vA; tB += vB; }
        }
        if (lane == 31) { ws0[wid] = tA; ws1[wid] = tB; }
        __syncthreads();                                   // bar1

        // Refill slot s with stage p+2. Safe: every thread's LDS of slot s
        // completed before bar1 (scan consumed the values). Commit an empty
        // group otherwise to keep wait_group<1> arithmetic uniform.
        if (p + 2 < PAIRS) {
            int ia = (row + 4) * WW + tid * 4;
            cp16(&tile[s][0][tid], dbase + ia);
            cp16(&tile[s][1][tid], fbase + ia);
            cp16(&tile[s][2][tid], dbase + ia + WW);
            cp16(&tile[s][3][tid], fbase + ia + WW);
        }
        cp_commit();

        float wb0 = 0.0f, wb1 = 0.0f;
        #pragma unroll
        for (int wv = 0; wv < NWARPS; ++wv)
            if (wv < wid) { wb0 += ws0[wv]; wb1 += ws1[wv]; }

        float base0 = wb0 + (tA - a3);
        float base1 = wb1 + (tB - b3);
        int xi = tid << 2;
        S0[xi + 1] = base0 + a0;
        S0[xi + 2] = base0 + a1;
        S0[xi + 3] = base0 + a2;
        S0[xi + 4] = base0 + a3;
        S1[xi + 1] = base1 + b0;
        S1[xi + 2] = base1 + b1;
        S1[xi + 3] = base1 + b2;
        S1[xi + 4] = base1 + b3;
        if (tid == 0) { S0[0] = 0.0f; S1[0] = 0.0f; }
        __syncthreads();                                   // bar2

        // Box accumulation for both rows. No trailing barrier needed: ws is
        // only read between bar1/bar2, and S(p+1) is only written after
        // bar1(p+1), which follows every thread's gather of S(p).
        if (row     >= c0.z && row     < c0.w) acc0 += S0[c0.y] - S0[c0.x];
        if (row + 1 >= c0.z && row + 1 < c0.w) acc0 += S1[c0.y] - S1[c0.x];
        if (row     >= c1.z && row     < c1.w) acc1 += S0[c1.y] - S0[c1.x];
        if (row + 1 >= c1.z && row + 1 < c1.w) acc1 += S1[c1.y] - S1[c1.x];
    }

    if (acc0 != 0.0f)            atomicAdd(&g_boxsum[b * NN + n0], acc0);
    if (n1 < NN && acc1 != 0.0f) atomicAdd(&g_boxsum[b * NN + n1], acc1);
}

// ---------------------------------------------------------------------------
// Reduce: 38 CTAs, ONE box per thread (full wave, no serial loop). Each
// thread recomputes validity/weight, folds in its box sum, resets g_boxsum.
// One atomicAdd per CTA into g_total.
// ---------------------------------------------------------------------------
__global__ __launch_bounds__(THREADS)
void reduce_kernel(const float* __restrict__ boxes,
                   const float* __restrict__ conf) {
    const int i = blockIdx.x * THREADS + threadIdx.x;
    float s = 0.0f;
    if (i < NB) {
        float v = g_boxsum[i];
        g_boxsum[i] = 0.0f;                       // reset for next replay
        int4 c   = box_coords(((const float4*)boxes)[i]);
        float cf = conf[i];
        if ((cf >= 0.3f) && (c.y > c.x) && (c.w > c.z)) {
            float area = (float)((c.w - c.z) * (c.y - c.x));
            s = fmaxf(v, 0.0f) * cf / area;       // relu((f-d)/area)*conf
        }
    }
    __shared__ float sm[NWARPS];
    #pragma unroll
    for (int o = 16; o > 0; o >>= 1) s += __shfl_down_sync(0xffffffffu, s, o);
    if ((threadIdx.x & 31) == 0) sm[threadIdx.x >> 5] = s;
    __syncthreads();
    if (threadIdx.x < 32) {
        s = (threadIdx.x < NWARPS) ? sm[threadIdx.x] : 0.0f;
        #pragma unroll
        for (int o = NWARPS / 2; o > 0; o >>= 1)
            s += __shfl_down_sync(0xffffffffu, s, o);
        if (threadIdx.x == 0 && s != 0.0f) atomicAdd(&g_total, s);
    }
}

// ---------------------------------------------------------------------------
// Finalize: write scalar output, re-zero g_total for the next graph replay.
// ---------------------------------------------------------------------------
__global__ void finalize_kernel(float* __restrict__ out) {
    out[0] = g_total / (float)NB;
    g_total = 0.0f;
}

// ---------------------------------------------------------------------------
extern "C" void kernel_launch(void* const* d_in, const int* in_sizes, int n_in,
                              void* d_out, int out_size) {
    const float* boxes = (const float*)d_in[0];   // (32,300,4)
    const float* conf  = (const float*)d_in[1];   // (32,300)
    const float* seg   = (const float*)d_in[2];   // (32,3,1024,1024)
    float* out = (float*)d_out;

    strip_kernel<<<BB * (HH / ROWS_PER_BLK), THREADS>>>(seg, boxes);
    reduce_kernel<<<(NB + THREADS - 1) / THREADS, THREADS>>>(boxes, conf);
    finalize_kernel<<<1, 1>>>(out);
}

// round 7
// speedup vs baseline: 1.5665x; 1.0421x over previous
#include <cuda_runtime.h>

#define BB 32
#define NN 300
#define HH 1024
#define WW 1024
#define HWP (HH * WW)
#define NB (BB * NN)          // 9600 boxes total
#define ROWS_PER_BLK 16
#define PAIRS (ROWS_PER_BLK / 2)
#define THREADS 256
#define NWARPS (THREADS / 32)
#define STAGES 2

// Scratch: per-box accumulators + scalar total. Zero-initialized at module
// load; reduce/finalize re-zero them, so every graph replay starts clean.
__device__ float g_boxsum[NB];
__device__ float g_total;

__device__ __forceinline__ void cp16(void* dst_smem, const void* src) {
    unsigned d = (unsigned)__cvta_generic_to_shared(dst_smem);
    asm volatile("cp.async.cg.shared.global [%0], [%1], 16;" :: "r"(d), "l"(src));
}
__device__ __forceinline__ void cp_commit() {
    asm volatile("cp.async.commit_group;" ::: "memory");
}
template <int N>
__device__ __forceinline__ void cp_wait() {
    asm volatile("cp.async.wait_group %0;" :: "n"(N) : "memory");
}

__device__ __forceinline__ int4 box_coords(const float4 bx) {
    // cxcywh -> xyxy pixel indices, trunc toward zero (C cast == jnp.trunc
    // for this range), clamp to [0, dim-1]. Validity handled in reduce.
    int x1 = min(max((int)((bx.x - 0.5f * bx.z) * (float)WW), 0), WW - 1);
    int x2 = min(max((int)((bx.x + 0.5f * bx.z) * (float)WW), 0), WW - 1);
    int y1 = min(max((int)((bx.y - 0.5f * bx.w) * (float)HH), 0), HH - 1);
    int y2 = min(max((int)((bx.y + 0.5f * bx.w) * (float)HH), 0), HH - 1);
    return make_int4(x1, x2, y1, y2);   // (x1, x2, y1, y2)
}

// ---------------------------------------------------------------------------
// Strip kernel: one CTA per (batch, 16-row strip). Tiles stage through SMEM
// via cp.async double-buffer. Per row-PAIR: two interleaved warp scans build
// INCLUSIVE prefixes I0/I1 (aligned STS.128 stores); each thread folds
// I[x2-1] - m*I[x1-1] for its <=2 owned boxes into registers. Two barriers
// per pair. One atomicAdd per (box, strip) at the end.
// ---------------------------------------------------------------------------
__global__ __launch_bounds__(THREADS, 5)
void strip_kernel(const float* __restrict__ seg,
                  const float* __restrict__ boxes) {
    __shared__ float4 tile[STAGES][4][THREADS];  // [stage][dA,fA,dB,fB][tid]
    __shared__ float4 S0[WW / 4];                // inclusive prefix, row A
    __shared__ float4 S1[WW / 4];                // inclusive prefix, row B
    __shared__ float ws0[NWARPS];
    __shared__ float ws1[NWARPS];

    const int b    = blockIdx.x / (HH / ROWS_PER_BLK);
    const int rb   = blockIdx.x % (HH / ROWS_PER_BLK);
    const int row0 = rb * ROWS_PER_BLK;
    const int tid  = threadIdx.x;
    const int lane = tid & 31;
    const int wid  = tid >> 5;

    const float* dbase = seg + (size_t)b * 3 * HWP + 1 * HWP;
    const float* fbase = seg + (size_t)b * 3 * HWP + 2 * HWP;

    // Prologue: issue stages 0 and 1 (one commit group per stage).
    {
        int ia = row0 * WW + tid * 4;
        cp16(&tile[0][0][tid], dbase + ia);
        cp16(&tile[0][1][tid], fbase + ia);
        cp16(&tile[0][2][tid], dbase + ia + WW);
        cp16(&tile[0][3][tid], fbase + ia + WW);
        cp_commit();
        ia += 2 * WW;
        cp16(&tile[1][0][tid], dbase + ia);
        cp16(&tile[1][1][tid], fbase + ia);
        cp16(&tile[1][2][tid], dbase + ia + WW);
        cp16(&tile[1][3][tid], fbase + ia + WW);
        cp_commit();
    }

    // Owned boxes (<=2 per thread): coords + gather indices computed once
    // (overlaps with the in-flight cp.async stages).
    // Gather: sum[x1,x2) = I[x2-1] - (x1>0)*I[x1-1].
    const int n0 = tid;
    const int n1 = tid + THREADS;
    int4 c0 = box_coords(((const float4*)boxes)[b * NN + n0]);
    int4 c1 = (n1 < NN) ? box_coords(((const float4*)boxes)[b * NN + n1])
                        : make_int4(0, 0, 0, 0);   // y1=y2=0 -> never matches
    const int   xe0 = c0.y - 1, xs0 = max(c0.x - 1, 0);
    const float m0  = (c0.x > 0) ? 1.0f : 0.0f;
    const int   xe1 = c1.y - 1, xs1 = max(c1.x - 1, 0);
    const float m1  = (c1.x > 0) ? 1.0f : 0.0f;
    float acc0 = 0.0f, acc1 = 0.0f;

    const float* S0f = (const float*)S0;
    const float* S1f = (const float*)S1;

    #pragma unroll
    for (int p = 0; p < PAIRS; ++p) {
        const int row = row0 + 2 * p;
        const int s   = p & 1;

        // Stage p complete (each thread reads only bytes its own cp.async
        // wrote, so wait_group suffices -- no barrier).
        cp_wait<1>();
        float4 dA = tile[s][0][tid];
        float4 fA = tile[s][1][tid];
        float4 dB = tile[s][2][tid];
        float4 fB = tile[s][3][tid];

        float a0 = fA.x - dA.x;
        float a1 = a0 + (fA.y - dA.y);
        float a2 = a1 + (fA.z - dA.z);
        float a3 = a2 + (fA.w - dA.w);
        float b0 = fB.x - dB.x;
        float b1 = b0 + (fB.y - dB.y);
        float b2 = b1 + (fB.z - dB.z);
        float b3 = b2 + (fB.w - dB.w);

        // Two interleaved warp-inclusive scans (shared shfl latency).
        float tA = a3, tB = b3;
        #pragma unroll
        for (int o = 1; o < 32; o <<= 1) {
            float vA = __shfl_up_sync(0xffffffffu, tA, o);
            float vB = __shfl_up_sync(0xffffffffu, tB, o);
            if (lane >= o) { tA += vA; tB += vB; }
        }
        if (lane == 31) { ws0[wid] = tA; ws1[wid] = tB; }
        __syncthreads();                                   // bar1

        // Refill slot s with stage p+2. Safe: every thread's LDS of slot s
        // completed before bar1 (scan consumed the values). Commit an empty
        // group otherwise to keep wait_group<1> arithmetic uniform.
        if (p + 2 < PAIRS) {
            int ia = (row + 4) * WW + tid * 4;
            cp16(&tile[s][0][tid], dbase + ia);
            cp16(&tile[s][1][tid], fbase + ia);
            cp16(&tile[s][2][tid], dbase + ia + WW);
            cp16(&tile[s][3][tid], fbase + ia + WW);
        }
        cp_commit();

        float wb0 = 0.0f, wb1 = 0.0f;
        #pragma unroll
        for (int wv = 0; wv < NWARPS; ++wv)
            if (wv < wid) { wb0 += ws0[wv]; wb1 += ws1[wv]; }

        const float base0 = wb0 + (tA - a3);
        const float base1 = wb1 + (tB - b3);
        // Inclusive prefix, 16B-aligned vector stores.
        S0[tid] = make_float4(base0 + a0, base0 + a1, base0 + a2, base0 + a3);
        S1[tid] = make_float4(base1 + b0, base1 + b1, base1 + b2, base1 + b3);
        __syncthreads();                                   // bar2

        // Box accumulation for both rows. No trailing barrier needed: ws is
        // only read between bar1/bar2, and S(p+1) is only written after
        // bar1(p+1), which follows every thread's gather of S(p).
        if (row     >= c0.z && row     < c0.w) acc0 += S0f[xe0] - m0 * S0f[xs0];
        if (row + 1 >= c0.z && row + 1 < c0.w) acc0 += S1f[xe0] - m0 * S1f[xs0];
        if (row     >= c1.z && row     < c1.w) acc1 += S0f[xe1] - m1 * S0f[xs1];
        if (row + 1 >= c1.z && row + 1 < c1.w) acc1 += S1f[xe1] - m1 * S1f[xs1];
    }

    if (acc0 != 0.0f)            atomicAdd(&g_boxsum[b * NN + n0], acc0);
    if (n1 < NN && acc1 != 0.0f) atomicAdd(&g_boxsum[b * NN + n1], acc1);
}

// ---------------------------------------------------------------------------
// Reduce: 38 CTAs, ONE box per thread (full wave, no serial loop). Each
// thread recomputes validity/weight, folds in its box sum, resets g_boxsum.
// One atomicAdd per CTA into g_total.
// ---------------------------------------------------------------------------
__global__ __launch_bounds__(THREADS)
void reduce_kernel(const float* __restrict__ boxes,
                   const float* __restrict__ conf) {
    const int i = blockIdx.x * THREADS + threadIdx.x;
    float s = 0.0f;
    if (i < NB) {
        float v = g_boxsum[i];
        g_boxsum[i] = 0.0f;                       // reset for next replay
        int4 c   = box_coords(((const float4*)boxes)[i]);
        float cf = conf[i];
        if ((cf >= 0.3f) && (c.y > c.x) && (c.w > c.z)) {
            float area = (float)((c.w - c.z) * (c.y - c.x));
            s = fmaxf(v, 0.0f) * cf / area;       // relu((f-d)/area)*conf
        }
    }
    __shared__ float sm[NWARPS];
    #pragma unroll
    for (int o = 16; o > 0; o >>= 1) s += __shfl_down_sync(0xffffffffu, s, o);
    if ((threadIdx.x & 31) == 0) sm[threadIdx.x >> 5] = s;
    __syncthreads();
    if (threadIdx.x < 32) {
        s = (threadIdx.x < NWARPS) ? sm[threadIdx.x] : 0.0f;
        #pragma unroll
        for (int o = NWARPS / 2; o > 0; o >>= 1)
            s += __shfl_down_sync(0xffffffffu, s, o);
        if (threadIdx.x == 0 && s != 0.0f) atomicAdd(&g_total, s);
    }
}

// ---------------------------------------------------------------------------
// Finalize: write scalar output, re-zero g_total for the next graph replay.
// ---------------------------------------------------------------------------
__global__ void finalize_kernel(float* __restrict__ out) {
    out[0] = g_total / (float)NB;
    g_total = 0.0f;
}

// ---------------------------------------------------------------------------
extern "C" void kernel_launch(void* const* d_in, const int* in_sizes, int n_in,
                              void* d_out, int out_size) {
    const float* boxes = (const float*)d_in[0];   // (32,300,4)
    const float* conf  = (const float*)d_in[1];   // (32,300)
    const float* seg   = (const float*)d_in[2];   // (32,3,1024,1024)
    float* out = (float*)d_out;

    strip_kernel<<<BB * (HH / ROWS_PER_BLK), THREADS>>>(seg, boxes);
    reduce_kernel<<<(NB + THREADS - 1) / THREADS, THREADS>>>(boxes, conf);
    finalize_kernel<<<1, 1>>>(out);
}